// round 10
// baseline (speedup 1.0000x reference)
#include <cuda_runtime.h>
#include <cuda_bf16.h>
#include <cstdint>

#define BATCH 8
#define NHID 256
#define LEN 2048
#define DD 512
#define DOUT 2048
#define MM (BATCH*LEN)

#define BM 128
#define BN 128
#define BK 32
#define NTHREADS 256
#define STAGES 3
#define MAT_BYTES 8192
#define STAGE_BYTES (4*MAT_BYTES)
#define SMEM_BYTES (STAGES*STAGE_BYTES)   // 96KB -> 2 CTA/SM
#define EPI_PITCH 132                      // floats; 528B rows, 16B aligned
#define PGRID 296                          // 148 SMs x 2 CTA

// fp32 scratch
__device__ __align__(128) float g_q[MM*DD];
__device__ __align__(128) float g_k[MM*DD];
__device__ __align__(128) float g_v[MM*DD];
// bf16 split operands
__device__ __align__(128) __nv_bfloat16 g_xt_hi[MM*NHID];
__device__ __align__(128) __nv_bfloat16 g_xt_lo[MM*NHID];
__device__ __align__(128) __nv_bfloat16 g_wq_hi[DD*NHID];
__device__ __align__(128) __nv_bfloat16 g_wq_lo[DD*NHID];
__device__ __align__(128) __nv_bfloat16 g_wk_hi[DD*NHID];
__device__ __align__(128) __nv_bfloat16 g_wk_lo[DD*NHID];
__device__ __align__(128) __nv_bfloat16 g_wv_hi[DD*NHID];
__device__ __align__(128) __nv_bfloat16 g_wv_lo[DD*NHID];
__device__ __align__(128) __nv_bfloat16 g_wo_hi[DOUT*DD];
__device__ __align__(128) __nv_bfloat16 g_wo_lo[DOUT*DD];
__device__ __align__(128) __nv_bfloat16 g_att_hi[MM*DD];
__device__ __align__(128) __nv_bfloat16 g_att_lo[MM*DD];

struct GemmArgs {
    const __nv_bfloat16* Ah; const __nv_bfloat16* Al;
    const __nv_bfloat16* Bh[3]; const __nv_bfloat16* Bl[3];
    const float* bias[3]; float* out[3];
};

__device__ __forceinline__ uint32_t s2u(const void* p){
    uint32_t a; asm("{ .reg .u64 t; cvta.to.shared.u64 t, %1; cvt.u32.u64 %0, t; }":"=r"(a):"l"(p)); return a; }
__device__ __forceinline__ void cpa16(uint32_t s, const void* g){
    asm volatile("cp.async.cg.shared.global [%0], [%1], 16;"::"r"(s),"l"(g):"memory"); }
#define CPA_COMMIT() asm volatile("cp.async.commit_group;":::"memory")
#define CPA_WAIT(n)  asm volatile("cp.async.wait_group %0;"::"n"(n):"memory")

__device__ __forceinline__ void ldm4(uint32_t a, uint32_t* r){
    asm volatile("ldmatrix.sync.aligned.m8n8.x4.shared.b16 {%0,%1,%2,%3}, [%4];"
        :"=r"(r[0]),"=r"(r[1]),"=r"(r[2]),"=r"(r[3]):"r"(a)); }
__device__ __forceinline__ void mma16816(float* d, const uint32_t* a,
                                         uint32_t b0, uint32_t b1){
    asm volatile("mma.sync.aligned.m16n8k16.row.col.f32.bf16.bf16.f32 "
        "{%0,%1,%2,%3}, {%4,%5,%6,%7}, {%8,%9}, {%0,%1,%2,%3};"
        :"+f"(d[0]),"+f"(d[1]),"+f"(d[2]),"+f"(d[3])
        :"r"(a[0]),"r"(a[1]),"r"(a[2]),"r"(a[3]),"r"(b0),"r"(b1)); }

// 16B-unit XOR swizzle: rows of 32 bf16 = 4 units; phys = r*4 + (u ^ ((r>>1)&3))
__device__ __forceinline__ uint32_t swz(int r, int u){
    return (uint32_t)((r*4 + (u ^ ((r>>1)&3))) * 16);
}

__device__ __forceinline__ void fill_stage(uint32_t sbase,
        const __nv_bfloat16* __restrict__ Ah, const __nv_bfloat16* __restrict__ Al,
        const __nv_bfloat16* __restrict__ Bh, const __nv_bfloat16* __restrict__ Bl,
        int K, int m0, int n0, int k0, int tid){
    #pragma unroll
    for (int j = 0; j < 2; j++){
        int i = tid + j*NTHREADS;          // 0..511
        int r = i >> 2, u = i & 3;
        uint32_t sw = swz(r, u);
        size_t gA = (size_t)(m0 + r)*K + k0 + u*8;
        size_t gB = (size_t)(n0 + r)*K + k0 + u*8;
        cpa16(sbase + 0*MAT_BYTES + sw, Ah + gA);
        cpa16(sbase + 1*MAT_BYTES + sw, Al + gA);
        cpa16(sbase + 2*MAT_BYTES + sw, Bh + gB);
        cpa16(sbase + 3*MAT_BYTES + sw, Bl + gB);
    }
}

// Persistent GEMM.
// mode 0: C[m0+row, n0+col] -> out[(m0+row)*DD + n0+col] + bias[n0+col]
// mode 1: C[m0+row(nout), n0+col(seq)] -> out[(b*DOUT + m0+row)*LEN + l0+col] + bias[m0+row]
__global__ __launch_bounds__(NTHREADS, 2)
void mma_gemm(const __grid_constant__ GemmArgs args, int K, int mode, int ntiles){
    extern __shared__ __align__(1024) char smem[];
    float* sf = (float*)smem;
    const uint32_t sb = s2u(smem);
    const int tid = threadIdx.x;
    const int wid = tid >> 5, lane = tid & 31;
    const int wm = (wid & 3) * 32;
    const int wn = (wid >> 2) * 64;
    const int NC = K / BK;

    const int g8 = lane >> 3;
    const int frag_row = ((g8 & 1) << 3) + (lane & 7);
    const int frag_u   = g8 >> 1;
    const int gq = lane >> 2, c2 = (lane & 3) * 2;

    for (int t = blockIdx.x; t < ntiles; t += gridDim.x){
        int m0, n0, z;
        if (mode == 0){
            z = t >> 9;
            int rem = t & 511;
            m0 = (rem >> 2) * BM;
            n0 = (rem & 3) * BN;
        } else {
            z = 0;
            m0 = (t & 15) * BM;      // nout tile (fast -> L2 reuse of att)
            n0 = (t >> 4) * BN;      // sequence tile
        }
        const __nv_bfloat16* __restrict__ Ah = args.Ah;
        const __nv_bfloat16* __restrict__ Al = args.Al;
        const __nv_bfloat16* __restrict__ Bh = args.Bh[z];
        const __nv_bfloat16* __restrict__ Bl = args.Bl[z];
        const float* __restrict__ bias = args.bias[z];
        float* __restrict__ out = args.out[z];

        float acc[2][8][4];
        #pragma unroll
        for (int i = 0; i < 2; i++)
            #pragma unroll
            for (int j = 0; j < 8; j++)
                #pragma unroll
                for (int q = 0; q < 4; q++) acc[i][j][q] = 0.f;

        #pragma unroll
        for (int c = 0; c < STAGES - 1; c++){
            fill_stage(sb + c*STAGE_BYTES, Ah, Al, Bh, Bl, K, m0, n0, c*BK, tid);
            CPA_COMMIT();
        }

        for (int c = 0; c < NC; c++){
            CPA_WAIT(STAGES - 2);
            __syncthreads();
            if (c + STAGES - 1 < NC)
                fill_stage(sb + ((c + STAGES - 1) % STAGES)*STAGE_BYTES,
                           Ah, Al, Bh, Bl, K, m0, n0, (c + STAGES - 1)*BK, tid);
            CPA_COMMIT();

            const uint32_t st = sb + (c % STAGES)*STAGE_BYTES;
            #pragma unroll
            for (int ks = 0; ks < 2; ks++){
                uint32_t ah[2][4];
                #pragma unroll
                for (int mf = 0; mf < 2; mf++)
                    ldm4(st + 0*MAT_BYTES + swz(wm + mf*16 + frag_row, ks*2 + frag_u), ah[mf]);
                uint32_t b4h[4][4];
                #pragma unroll
                for (int np = 0; np < 4; np++)
                    ldm4(st + 2*MAT_BYTES + swz(wn + np*16 + frag_row, ks*2 + frag_u), b4h[np]);
                #pragma unroll
                for (int np = 0; np < 4; np++)
                    #pragma unroll
                    for (int mf = 0; mf < 2; mf++){
                        mma16816(acc[mf][np*2],   ah[mf], b4h[np][0], b4h[np][2]);
                        mma16816(acc[mf][np*2+1], ah[mf], b4h[np][1], b4h[np][3]);
                    }
                uint32_t b4l[4][4];
                #pragma unroll
                for (int np = 0; np < 4; np++)
                    ldm4(st + 3*MAT_BYTES + swz(wn + np*16 + frag_row, ks*2 + frag_u), b4l[np]);
                #pragma unroll
                for (int np = 0; np < 4; np++)
                    #pragma unroll
                    for (int mf = 0; mf < 2; mf++){
                        mma16816(acc[mf][np*2],   ah[mf], b4l[np][0], b4l[np][2]);
                        mma16816(acc[mf][np*2+1], ah[mf], b4l[np][1], b4l[np][3]);
                    }
                uint32_t al[2][4];
                #pragma unroll
                for (int mf = 0; mf < 2; mf++)
                    ldm4(st + 1*MAT_BYTES + swz(wm + mf*16 + frag_row, ks*2 + frag_u), al[mf]);
                #pragma unroll
                for (int np = 0; np < 4; np++)
                    #pragma unroll
                    for (int mf = 0; mf < 2; mf++){
                        mma16816(acc[mf][np*2],   al[mf], b4h[np][0], b4h[np][2]);
                        mma16816(acc[mf][np*2+1], al[mf], b4h[np][1], b4h[np][3]);
                    }
            }
        }
        __syncthreads();   // compute done; smem free for staging

        // stage tile (with bias) into smem as fp32 [row][col], pitch EPI_PITCH
        #pragma unroll
        for (int mf = 0; mf < 2; mf++){
            int r0 = wm + mf*16 + gq;
            #pragma unroll
            for (int nf = 0; nf < 8; nf++){
                int col = wn + nf*8 + c2;
                float b0, b1, b2, b3;
                if (mode == 0){
                    b0 = __ldg(bias + n0 + col); b1 = __ldg(bias + n0 + col + 1);
                    b2 = b0; b3 = b1;
                } else {
                    b0 = __ldg(bias + m0 + r0);  b1 = b0;
                    b2 = __ldg(bias + m0 + r0 + 8); b3 = b2;
                }
                *reinterpret_cast<float2*>(&sf[r0*EPI_PITCH + col]) =
                    make_float2(acc[mf][nf][0] + b0, acc[mf][nf][1] + b1);
                *reinterpret_cast<float2*>(&sf[(r0+8)*EPI_PITCH + col]) =
                    make_float2(acc[mf][nf][2] + b2, acc[mf][nf][3] + b3);
            }
        }
        __syncthreads();

        // coalesced copy-out: 4096 float4 slots, 16 per thread
        if (mode == 0){
            #pragma unroll
            for (int i = 0; i < 16; i++){
                int f = tid + i*NTHREADS;
                int row = f >> 5, c4 = (f & 31) << 2;
                float4 v = *reinterpret_cast<const float4*>(&sf[row*EPI_PITCH + c4]);
                *reinterpret_cast<float4*>(&out[(size_t)(m0+row)*DD + n0 + c4]) = v;
            }
        } else {
            const int b = n0 >> 11, l0 = n0 & (LEN - 1);
            #pragma unroll
            for (int i = 0; i < 16; i++){
                int f = tid + i*NTHREADS;
                int row = f >> 5, c4 = (f & 31) << 2;
                float4 v = *reinterpret_cast<const float4*>(&sf[row*EPI_PITCH + c4]);
                *reinterpret_cast<float4*>(&out[((size_t)(b*DOUT + m0 + row))*LEN + l0 + c4]) = v;
            }
        }
        __syncthreads();   // staging reads done before next tile's fills
    }
}

// transpose + bf16 split: slab z of src [R][C] fp32 -> dst [C][R] bf16 hi/lo
__global__ __launch_bounds__(256)
void tsplit(const float* __restrict__ src, __nv_bfloat16* __restrict__ dhi,
            __nv_bfloat16* __restrict__ dlo, int R, int C){
    __shared__ float tile[32][33];
    const size_t zo = (size_t)blockIdx.z * R * C;
    const int c0 = blockIdx.x*32, r0 = blockIdx.y*32;
    #pragma unroll
    for (int i = threadIdx.y; i < 32; i += 8)
        tile[i][threadIdx.x] = src[zo + (size_t)(r0+i)*C + c0 + threadIdx.x];
    __syncthreads();
    #pragma unroll
    for (int i = threadIdx.y; i < 32; i += 8){
        float v = tile[threadIdx.x][i];
        __nv_bfloat16 h = __float2bfloat16(v);
        __nv_bfloat16 lo = __float2bfloat16(v - __bfloat162float(h));
        const size_t o = zo + (size_t)(c0+i)*R + r0 + threadIdx.x;
        dhi[o] = h; dlo[o] = lo;
    }
}

// window-3 softmax attention; emits bf16-split att
__global__ __launch_bounds__(256)
void attn_kernel(){
    for (int m = blockIdx.x; m < MM; m += gridDim.x){
        const int b = m >> 11, l = m & (LEN-1);
        const int head = threadIdx.x >> 5, lane = threadIdx.x & 31;
        const size_t base = (size_t)m*DD + head*64 + lane*2;
        const float2 q = *reinterpret_cast<const float2*>(&g_q[base]);
        float s[3]; float2 vv[3];
        #pragma unroll
        for (int w = 0; w < 3; w++){
            const int lw = l + w - 1;
            float2 kk = make_float2(0.f,0.f), v2 = make_float2(0.f,0.f);
            if (lw >= 0 && lw < LEN){
                const size_t off = (size_t)(b*LEN+lw)*DD + head*64 + lane*2;
                kk = *reinterpret_cast<const float2*>(&g_k[off]);
                v2 = *reinterpret_cast<const float2*>(&g_v[off]);
            }
            float p = q.x*kk.x + q.y*kk.y;
            #pragma unroll
            for (int o = 16; o; o >>= 1) p += __shfl_xor_sync(0xffffffffu, p, o);
            s[w] = p * 0.125f; vv[w] = v2;
        }
        const float mx = fmaxf(s[0], fmaxf(s[1], s[2]));
        const float e0 = __expf(s[0]-mx), e1 = __expf(s[1]-mx), e2 = __expf(s[2]-mx);
        const float inv = 1.f/(e0+e1+e2);
        const float ox = (e0*vv[0].x + e1*vv[1].x + e2*vv[2].x)*inv;
        const float oy = (e0*vv[0].y + e1*vv[1].y + e2*vv[2].y)*inv;
        __nv_bfloat16 hx = __float2bfloat16(ox), hy = __float2bfloat16(oy);
        __nv_bfloat162 hi; hi.x = hx; hi.y = hy;
        __nv_bfloat162 lo;
        lo.x = __float2bfloat16(ox - __bfloat162float(hx));
        lo.y = __float2bfloat16(oy - __bfloat162float(hy));
        *reinterpret_cast<__nv_bfloat162*>(&g_att_hi[base]) = hi;
        *reinterpret_cast<__nv_bfloat162*>(&g_att_lo[base]) = lo;
    }
}

extern "C" void kernel_launch(void* const* d_in, const int* in_sizes, int n_in,
                              void* d_out, int out_size){
    const float* x  = (const float*)d_in[0];
    const float* Wq = (const float*)d_in[1];
    const float* bq = (const float*)d_in[2];
    const float* Wk = (const float*)d_in[3];
    const float* bk = (const float*)d_in[4];
    const float* Wv = (const float*)d_in[5];
    const float* bv = (const float*)d_in[6];
    const float* Wo = (const float*)d_in[7];
    const float* bo = (const float*)d_in[8];
    float* out = (float*)d_out;

    void *xh,*xl,*qh,*ql,*kh,*kl,*vh,*vl,*oh,*ol,*ath,*atl,*pq,*pk,*pv;
    cudaGetSymbolAddress(&xh, g_xt_hi);  cudaGetSymbolAddress(&xl, g_xt_lo);
    cudaGetSymbolAddress(&qh, g_wq_hi);  cudaGetSymbolAddress(&ql, g_wq_lo);
    cudaGetSymbolAddress(&kh, g_wk_hi);  cudaGetSymbolAddress(&kl, g_wk_lo);
    cudaGetSymbolAddress(&vh, g_wv_hi);  cudaGetSymbolAddress(&vl, g_wv_lo);
    cudaGetSymbolAddress(&oh, g_wo_hi);  cudaGetSymbolAddress(&ol, g_wo_lo);
    cudaGetSymbolAddress(&ath, g_att_hi); cudaGetSymbolAddress(&atl, g_att_lo);
    cudaGetSymbolAddress(&pq, g_q); cudaGetSymbolAddress(&pk, g_k);
    cudaGetSymbolAddress(&pv, g_v);

    cudaFuncSetAttribute(mma_gemm, cudaFuncAttributeMaxDynamicSharedMemorySize, SMEM_BYTES);

    dim3 tb(32, 8);
    tsplit<<<dim3(LEN/32, NHID/32, BATCH), tb>>>(x, (__nv_bfloat16*)xh, (__nv_bfloat16*)xl, NHID, LEN);
    tsplit<<<dim3(DD/32, NHID/32, 1), tb>>>(Wq, (__nv_bfloat16*)qh, (__nv_bfloat16*)ql, NHID, DD);
    tsplit<<<dim3(DD/32, NHID/32, 1), tb>>>(Wk, (__nv_bfloat16*)kh, (__nv_bfloat16*)kl, NHID, DD);
    tsplit<<<dim3(DD/32, NHID/32, 1), tb>>>(Wv, (__nv_bfloat16*)vh, (__nv_bfloat16*)vl, NHID, DD);
    tsplit<<<dim3(DOUT/32, DD/32, 1), tb>>>(Wo, (__nv_bfloat16*)oh, (__nv_bfloat16*)ol, DD, DOUT);

    GemmArgs a1;
    a1.Ah = (const __nv_bfloat16*)xh; a1.Al = (const __nv_bfloat16*)xl;
    a1.Bh[0] = (const __nv_bfloat16*)qh; a1.Bl[0] = (const __nv_bfloat16*)ql;
    a1.Bh[1] = (const __nv_bfloat16*)kh; a1.Bl[1] = (const __nv_bfloat16*)kl;
    a1.Bh[2] = (const __nv_bfloat16*)vh; a1.Bl[2] = (const __nv_bfloat16*)vl;
    a1.bias[0] = bq; a1.bias[1] = bk; a1.bias[2] = bv;
    a1.out[0] = (float*)pq; a1.out[1] = (float*)pk; a1.out[2] = (float*)pv;
    mma_gemm<<<PGRID, NTHREADS, SMEM_BYTES>>>(a1, NHID, 0, (MM/BM)*(DD/BN)*3);

    attn_kernel<<<2048, 256>>>();

    GemmArgs a2;
    a2.Ah = (const __nv_bfloat16*)oh; a2.Al = (const __nv_bfloat16*)ol;
    a2.Bh[0] = (const __nv_bfloat16*)ath; a2.Bl[0] = (const __nv_bfloat16*)atl;
    a2.Bh[1] = a2.Bh[0]; a2.Bl[1] = a2.Bl[0];
    a2.Bh[2] = a2.Bh[0]; a2.Bl[2] = a2.Bl[0];
    a2.bias[0] = bo; a2.bias[1] = bo; a2.bias[2] = bo;
    a2.out[0] = out; a2.out[1] = out; a2.out[2] = out;
    mma_gemm<<<PGRID, NTHREADS, SMEM_BYTES>>>(a2, DD, 1, (DOUT/BM)*(MM/BN));
}

// round 11
// speedup vs baseline: 1.4488x; 1.4488x over previous
#include <cuda_runtime.h>
#include <cuda_fp16.h>
#include <cstdint>

#define BATCH 8
#define NHID 256
#define LEN 2048
#define DD 512
#define DOUT 2048
#define MM (BATCH*LEN)

#define BM 128
#define BN 128
#define BK 32
#define NTHREADS 256
#define STAGES 4
#define MAT_BYTES 8192                    // 128 rows x 32 halves x 2B
#define STAGE_BYTES (3*MAT_BYTES)         // A_hi, A_lo, B_hi
#define SMEM_BYTES (STAGES*STAGE_BYTES)   // 96KB -> 2 CTA/SM

// fp32 scratch
__device__ __align__(128) float g_q[MM*DD];
__device__ __align__(128) float g_k[MM*DD];
__device__ __align__(128) float g_v[MM*DD];
// fp16 split operands (A side gets hi+lo; B side hi only is consumed,
// but keep lo arrays for the GEMM2 A-side = Wo which needs hi/lo too)
__device__ __align__(128) __half g_xt_hi[MM*NHID];
__device__ __align__(128) __half g_xt_lo[MM*NHID];
__device__ __align__(128) __half g_wq_hi[DD*NHID];
__device__ __align__(128) __half g_wk_hi[DD*NHID];
__device__ __align__(128) __half g_wv_hi[DD*NHID];
__device__ __align__(128) __half g_wo_hi[DOUT*DD];
__device__ __align__(128) __half g_wo_lo[DOUT*DD];
__device__ __align__(128) __half g_att_hi[MM*DD];

struct GemmArgs {
    const __half* Ah; const __half* Al;
    const __half* Bh[3];
    const float* bias[3]; float* out[3];
};

__device__ __forceinline__ uint32_t s2u(const void* p){
    uint32_t a; asm("{ .reg .u64 t; cvta.to.shared.u64 t, %1; cvt.u32.u64 %0, t; }":"=r"(a):"l"(p)); return a; }
__device__ __forceinline__ void cpa16(uint32_t s, const void* g){
    asm volatile("cp.async.cg.shared.global [%0], [%1], 16;"::"r"(s),"l"(g):"memory"); }
#define CPA_COMMIT() asm volatile("cp.async.commit_group;":::"memory")
#define CPA_WAIT(n)  asm volatile("cp.async.wait_group %0;"::"n"(n):"memory")

__device__ __forceinline__ void ldm4(uint32_t a, uint32_t* r){
    asm volatile("ldmatrix.sync.aligned.m8n8.x4.shared.b16 {%0,%1,%2,%3}, [%4];"
        :"=r"(r[0]),"=r"(r[1]),"=r"(r[2]),"=r"(r[3]):"r"(a)); }
__device__ __forceinline__ void mma16816(float* d, const uint32_t* a,
                                         uint32_t b0, uint32_t b1){
    asm volatile("mma.sync.aligned.m16n8k16.row.col.f32.f16.f16.f32 "
        "{%0,%1,%2,%3}, {%4,%5,%6,%7}, {%8,%9}, {%0,%1,%2,%3};"
        :"+f"(d[0]),"+f"(d[1]),"+f"(d[2]),"+f"(d[3])
        :"r"(a[0]),"r"(a[1]),"r"(a[2]),"r"(a[3]),"r"(b0),"r"(b1)); }

// 16B-unit XOR swizzle: rows of 32 halves = 4 units; phys = r*4 + (u ^ ((r>>1)&3))
__device__ __forceinline__ uint32_t swz(int r, int u){
    return (uint32_t)((r*4 + (u ^ ((r>>1)&3))) * 16);
}

__device__ __forceinline__ void fill_stage(uint32_t sbase,
        const __half* __restrict__ Ah, const __half* __restrict__ Al,
        const __half* __restrict__ Bh,
        int K, int m0, int n0, int k0, int tid){
    #pragma unroll
    for (int j = 0; j < 2; j++){
        int i = tid + j*NTHREADS;          // 0..511
        int r = i >> 2, u = i & 3;
        uint32_t sw = swz(r, u);
        size_t gA = (size_t)(m0 + r)*K + k0 + u*8;
        size_t gB = (size_t)(n0 + r)*K + k0 + u*8;
        cpa16(sbase + 0*MAT_BYTES + sw, Ah + gA);
        cpa16(sbase + 1*MAT_BYTES + sw, Al + gA);
        cpa16(sbase + 2*MAT_BYTES + sw, Bh + gB);
    }
}

// mode 0: out[(m0+r)*DD + col] + bias[col]     (GEMM1)
// mode 1: out[(b*DOUT + r)*LEN + l] + bias[r]  (GEMM2, col=seq)
__global__ __launch_bounds__(NTHREADS, 2)
void mma_gemm(const __grid_constant__ GemmArgs args, int K, int mode){
    extern __shared__ __align__(1024) char smem[];
    const int z = blockIdx.z;
    const __half* __restrict__ Ah = args.Ah;
    const __half* __restrict__ Al = args.Al;
    const __half* __restrict__ Bh = args.Bh[z];
    const float* __restrict__ bias = args.bias[z];
    float* __restrict__ out = args.out[z];

    const uint32_t sb = s2u(smem);
    const int tid = threadIdx.x;
    const int wid = tid >> 5, lane = tid & 31;
    const int wm = (wid & 3) * 32;        // warp m offset
    const int wn = (wid >> 2) * 64;       // warp n offset
    const int m0 = blockIdx.y * BM;
    const int n0 = blockIdx.x * BN;
    const int NC = K / BK;

    const int g8 = lane >> 3;
    const int frag_row = ((g8 & 1) << 3) + (lane & 7);
    const int frag_u   = g8 >> 1;

    float acc[2][8][4];
    #pragma unroll
    for (int i = 0; i < 2; i++)
        #pragma unroll
        for (int j = 0; j < 8; j++)
            #pragma unroll
            for (int q = 0; q < 4; q++) acc[i][j][q] = 0.f;

    #pragma unroll
    for (int c = 0; c < STAGES - 1; c++){
        fill_stage(sb + c*STAGE_BYTES, Ah, Al, Bh, K, m0, n0, c*BK, tid);
        CPA_COMMIT();
    }

    for (int c = 0; c < NC; c++){
        CPA_WAIT(STAGES - 2);
        __syncthreads();
        if (c + STAGES - 1 < NC)
            fill_stage(sb + ((c + STAGES - 1) % STAGES)*STAGE_BYTES,
                       Ah, Al, Bh, K, m0, n0, (c + STAGES - 1)*BK, tid);
        CPA_COMMIT();

        const uint32_t st = sb + (c % STAGES)*STAGE_BYTES;
        #pragma unroll
        for (int ks = 0; ks < 2; ks++){
            uint32_t ah[2][4], al[2][4];
            #pragma unroll
            for (int mf = 0; mf < 2; mf++){
                uint32_t sw = swz(wm + mf*16 + frag_row, ks*2 + frag_u);
                ldm4(st + 0*MAT_BYTES + sw, ah[mf]);
                ldm4(st + 1*MAT_BYTES + sw, al[mf]);
            }
            #pragma unroll
            for (int np = 0; np < 4; np++){
                uint32_t sw = swz(wn + np*16 + frag_row, ks*2 + frag_u);
                uint32_t b4h[4];
                ldm4(st + 2*MAT_BYTES + sw, b4h);
                #pragma unroll
                for (int mf = 0; mf < 2; mf++){
                    float* ae = acc[mf][np*2];
                    float* ao = acc[mf][np*2 + 1];
                    mma16816(ae, ah[mf], b4h[0], b4h[2]);
                    mma16816(ae, al[mf], b4h[0], b4h[2]);
                    mma16816(ao, ah[mf], b4h[1], b4h[3]);
                    mma16816(ao, al[mf], b4h[1], b4h[3]);
                }
            }
        }
        __syncthreads();
    }

    // epilogue (direct, round-6 style)
    const int gq = lane >> 2, c2 = (lane & 3) * 2;
    if (mode == 0){
        #pragma unroll
        for (int mf = 0; mf < 2; mf++){
            int r = m0 + wm + mf*16 + gq;
            #pragma unroll
            for (int nf = 0; nf < 8; nf++){
                int col = n0 + wn + nf*8 + c2;
                float b0 = __ldg(bias + col), b1 = __ldg(bias + col + 1);
                *reinterpret_cast<float2*>(&out[(size_t)r*DD + col]) =
                    make_float2(acc[mf][nf][0] + b0, acc[mf][nf][1] + b1);
                *reinterpret_cast<float2*>(&out[(size_t)(r+8)*DD + col]) =
                    make_float2(acc[mf][nf][2] + b0, acc[mf][nf][3] + b1);
            }
        }
    } else {
        #pragma unroll
        for (int mf = 0; mf < 2; mf++){
            int r = m0 + wm + mf*16 + gq;
            float br0 = __ldg(bias + r), br1 = __ldg(bias + r + 8);
            #pragma unroll
            for (int nf = 0; nf < 8; nf++){
                int col = n0 + wn + nf*8 + c2;     // sequence index
                int b = col >> 11, l = col & (LEN - 1);
                *reinterpret_cast<float2*>(&out[((size_t)(b*DOUT + r))*LEN + l]) =
                    make_float2(acc[mf][nf][0] + br0, acc[mf][nf][1] + br0);
                *reinterpret_cast<float2*>(&out[((size_t)(b*DOUT + r + 8))*LEN + l]) =
                    make_float2(acc[mf][nf][2] + br1, acc[mf][nf][3] + br1);
            }
        }
    }
}

// transpose + fp16 split (hi + optional lo): src [R][C] fp32 -> dst [C][R]
__global__ __launch_bounds__(256)
void tsplit(const float* __restrict__ src, __half* __restrict__ dhi,
            __half* __restrict__ dlo, int R, int C){
    __shared__ float tile[32][33];
    const size_t zo = (size_t)blockIdx.z * R * C;
    const int c0 = blockIdx.x*32, r0 = blockIdx.y*32;
    #pragma unroll
    for (int i = threadIdx.y; i < 32; i += 8)
        tile[i][threadIdx.x] = src[zo + (size_t)(r0+i)*C + c0 + threadIdx.x];
    __syncthreads();
    #pragma unroll
    for (int i = threadIdx.y; i < 32; i += 8){
        float v = tile[threadIdx.x][i];
        __half h = __float2half(v);
        const size_t o = zo + (size_t)(c0+i)*R + r0 + threadIdx.x;
        dhi[o] = h;
        if (dlo) dlo[o] = __float2half(v - __half2float(h));
    }
}

// window-3 softmax attention; emits fp16 att (hi only; att is B-side of GEMM2)
__global__ __launch_bounds__(256)
void attn_kernel(){
    for (int m = blockIdx.x; m < MM; m += gridDim.x){
        const int b = m >> 11, l = m & (LEN-1);
        const int head = threadIdx.x >> 5, lane = threadIdx.x & 31;
        const size_t base = (size_t)m*DD + head*64 + lane*2;
        const float2 q = *reinterpret_cast<const float2*>(&g_q[base]);
        float s[3]; float2 vv[3];
        #pragma unroll
        for (int w = 0; w < 3; w++){
            const int lw = l + w - 1;
            float2 kk = make_float2(0.f,0.f), v2 = make_float2(0.f,0.f);
            if (lw >= 0 && lw < LEN){
                const size_t off = (size_t)(b*LEN+lw)*DD + head*64 + lane*2;
                kk = *reinterpret_cast<const float2*>(&g_k[off]);
                v2 = *reinterpret_cast<const float2*>(&g_v[off]);
            }
            float p = q.x*kk.x + q.y*kk.y;
            #pragma unroll
            for (int o = 16; o; o >>= 1) p += __shfl_xor_sync(0xffffffffu, p, o);
            s[w] = p * 0.125f; vv[w] = v2;
        }
        const float mx = fmaxf(s[0], fmaxf(s[1], s[2]));
        const float e0 = __expf(s[0]-mx), e1 = __expf(s[1]-mx), e2 = __expf(s[2]-mx);
        const float inv = 1.f/(e0+e1+e2);
        const float ox = (e0*vv[0].x + e1*vv[1].x + e2*vv[2].x)*inv;
        const float oy = (e0*vv[0].y + e1*vv[1].y + e2*vv[2].y)*inv;
        __half2 hi; hi.x = __float2half(ox); hi.y = __float2half(oy);
        *reinterpret_cast<__half2*>(&g_att_hi[base]) = hi;
    }
}

extern "C" void kernel_launch(void* const* d_in, const int* in_sizes, int n_in,
                              void* d_out, int out_size){
    const float* x  = (const float*)d_in[0];
    const float* Wq = (const float*)d_in[1];
    const float* bq = (const float*)d_in[2];
    const float* Wk = (const float*)d_in[3];
    const float* bk = (const float*)d_in[4];
    const float* Wv = (const float*)d_in[5];
    const float* bv = (const float*)d_in[6];
    const float* Wo = (const float*)d_in[7];
    const float* bo = (const float*)d_in[8];
    float* out = (float*)d_out;

    void *xh,*xl,*qh,*kh,*vh,*oh,*ol,*ath,*pq,*pk,*pv;
    cudaGetSymbolAddress(&xh, g_xt_hi);  cudaGetSymbolAddress(&xl, g_xt_lo);
    cudaGetSymbolAddress(&qh, g_wq_hi);
    cudaGetSymbolAddress(&kh, g_wk_hi);
    cudaGetSymbolAddress(&vh, g_wv_hi);
    cudaGetSymbolAddress(&oh, g_wo_hi);  cudaGetSymbolAddress(&ol, g_wo_lo);
    cudaGetSymbolAddress(&ath, g_att_hi);
    cudaGetSymbolAddress(&pq, g_q); cudaGetSymbolAddress(&pk, g_k);
    cudaGetSymbolAddress(&pv, g_v);

    cudaFuncSetAttribute(mma_gemm, cudaFuncAttributeMaxDynamicSharedMemorySize, SMEM_BYTES);

    dim3 tb(32, 8);
    // x split hi+lo (A-side of GEMM1)
    tsplit<<<dim3(LEN/32, NHID/32, BATCH), tb>>>(x, (__half*)xh, (__half*)xl, NHID, LEN);
    // weights: hi only (B-side of GEMM1)
    tsplit<<<dim3(DD/32, NHID/32, 1), tb>>>(Wq, (__half*)qh, (__half*)nullptr, NHID, DD);
    tsplit<<<dim3(DD/32, NHID/32, 1), tb>>>(Wk, (__half*)kh, (__half*)nullptr, NHID, DD);
    tsplit<<<dim3(DD/32, NHID/32, 1), tb>>>(Wv, (__half*)vh, (__half*)nullptr, NHID, DD);
    // Wo: hi+lo (A-side of GEMM2)
    tsplit<<<dim3(DOUT/32, DD/32, 1), tb>>>(Wo, (__half*)oh, (__half*)ol, DD, DOUT);

    GemmArgs a1;
    a1.Ah = (const __half*)xh; a1.Al = (const __half*)xl;
    a1.Bh[0] = (const __half*)qh;
    a1.Bh[1] = (const __half*)kh;
    a1.Bh[2] = (const __half*)vh;
    a1.bias[0] = bq; a1.bias[1] = bk; a1.bias[2] = bv;
    a1.out[0] = (float*)pq; a1.out[1] = (float*)pk; a1.out[2] = (float*)pv;
    mma_gemm<<<dim3(DD/BN, MM/BM, 3), NTHREADS, SMEM_BYTES>>>(a1, NHID, 0);

    attn_kernel<<<2048, 256>>>();

    GemmArgs a2;
    a2.Ah = (const __half*)oh; a2.Al = (const __half*)ol;
    a2.Bh[0] = (const __half*)ath;
    a2.Bh[1] = a2.Bh[0]; a2.Bh[2] = a2.Bh[0];
    a2.bias[0] = bo; a2.bias[1] = bo; a2.bias[2] = bo;
    a2.out[0] = out; a2.out[1] = out; a2.out[2] = out;
    mma_gemm<<<dim3(MM/BN, DOUT/BM, 1), NTHREADS, SMEM_BYTES>>>(a2, DD, 1);
}

// round 12
// speedup vs baseline: 2.1004x; 1.4497x over previous
#include <cuda_runtime.h>
#include <cuda_fp16.h>
#include <cstdint>

#define BATCH 8
#define NHID 256
#define LEN 2048
#define DD 512
#define DOUT 2048
#define MM (BATCH*LEN)

#define BM 128
#define BN 128
#define BK 32
#define NTHREADS 256
#define STAGES 5
#define MAT_BYTES 8192                    // 128 rows x 32 halves x 2B
#define STAGE_BYTES (2*MAT_BYTES)         // A_hi, B_hi
#define SMEM_BYTES (STAGES*STAGE_BYTES)   // 80KB -> 2 CTA/SM

// fp32 scratch
__device__ __align__(128) float g_q[MM*DD];
__device__ __align__(128) float g_k[MM*DD];
__device__ __align__(128) float g_v[MM*DD];
// fp16 operands
__device__ __align__(128) __half g_xt[MM*NHID];
__device__ __align__(128) __half g_wq[DD*NHID];
__device__ __align__(128) __half g_wk[DD*NHID];
__device__ __align__(128) __half g_wv[DD*NHID];
__device__ __align__(128) __half g_wo[DOUT*DD];
__device__ __align__(128) __half g_att[MM*DD];

struct GemmArgs {
    const __half* A;
    const __half* B[3];
    const float* bias[3]; float* out[3];
};

__device__ __forceinline__ uint32_t s2u(const void* p){
    uint32_t a; asm("{ .reg .u64 t; cvta.to.shared.u64 t, %1; cvt.u32.u64 %0, t; }":"=r"(a):"l"(p)); return a; }
__device__ __forceinline__ void cpa16(uint32_t s, const void* g){
    asm volatile("cp.async.cg.shared.global [%0], [%1], 16;"::"r"(s),"l"(g):"memory"); }
#define CPA_COMMIT() asm volatile("cp.async.commit_group;":::"memory")
#define CPA_WAIT(n)  asm volatile("cp.async.wait_group %0;"::"n"(n):"memory")

__device__ __forceinline__ void ldm4(uint32_t a, uint32_t* r){
    asm volatile("ldmatrix.sync.aligned.m8n8.x4.shared.b16 {%0,%1,%2,%3}, [%4];"
        :"=r"(r[0]),"=r"(r[1]),"=r"(r[2]),"=r"(r[3]):"r"(a)); }
__device__ __forceinline__ void mma16816(float* d, const uint32_t* a,
                                         uint32_t b0, uint32_t b1){
    asm volatile("mma.sync.aligned.m16n8k16.row.col.f32.f16.f16.f32 "
        "{%0,%1,%2,%3}, {%4,%5,%6,%7}, {%8,%9}, {%0,%1,%2,%3};"
        :"+f"(d[0]),"+f"(d[1]),"+f"(d[2]),"+f"(d[3])
        :"r"(a[0]),"r"(a[1]),"r"(a[2]),"r"(a[3]),"r"(b0),"r"(b1)); }

// 16B-unit XOR swizzle: rows of 32 halves = 4 units; phys = r*4 + (u ^ ((r>>1)&3))
__device__ __forceinline__ uint32_t swz(int r, int u){
    return (uint32_t)((r*4 + (u ^ ((r>>1)&3))) * 16);
}

__device__ __forceinline__ void fill_stage(uint32_t sbase,
        const __half* __restrict__ A, const __half* __restrict__ B,
        int K, int m0, int n0, int k0, int tid){
    #pragma unroll
    for (int j = 0; j < 2; j++){
        int i = tid + j*NTHREADS;          // 0..511
        int r = i >> 2, u = i & 3;
        uint32_t sw = swz(r, u);
        size_t gA = (size_t)(m0 + r)*K + k0 + u*8;
        size_t gB = (size_t)(n0 + r)*K + k0 + u*8;
        cpa16(sbase + 0*MAT_BYTES + sw, A + gA);
        cpa16(sbase + 1*MAT_BYTES + sw, B + gB);
    }
}

// mode 0: out[(m0+r)*DD + col] + bias[col]     (GEMM1)
// mode 1: out[(b*DOUT + r)*LEN + l] + bias[r]  (GEMM2, col=seq)
__global__ __launch_bounds__(NTHREADS, 2)
void mma_gemm(const __grid_constant__ GemmArgs args, int K, int mode){
    extern __shared__ __align__(1024) char smem[];
    const int z = blockIdx.z;
    const __half* __restrict__ A = args.A;
    const __half* __restrict__ B = args.B[z];
    const float* __restrict__ bias = args.bias[z];
    float* __restrict__ out = args.out[z];

    const uint32_t sb = s2u(smem);
    const int tid = threadIdx.x;
    const int wid = tid >> 5, lane = tid & 31;
    const int wm = (wid & 3) * 32;        // warp m offset
    const int wn = (wid >> 2) * 64;       // warp n offset
    const int m0 = blockIdx.y * BM;
    const int n0 = blockIdx.x * BN;
    const int NC = K / BK;

    const int g8 = lane >> 3;
    const int frag_row = ((g8 & 1) << 3) + (lane & 7);
    const int frag_u   = g8 >> 1;

    float acc[2][8][4];
    #pragma unroll
    for (int i = 0; i < 2; i++)
        #pragma unroll
        for (int j = 0; j < 8; j++)
            #pragma unroll
            for (int q = 0; q < 4; q++) acc[i][j][q] = 0.f;

    #pragma unroll
    for (int c = 0; c < STAGES - 1; c++){
        if (c < NC){
            fill_stage(sb + c*STAGE_BYTES, A, B, K, m0, n0, c*BK, tid);
        }
        CPA_COMMIT();
    }

    for (int c = 0; c < NC; c++){
        CPA_WAIT(STAGES - 2);
        __syncthreads();
        if (c + STAGES - 1 < NC)
            fill_stage(sb + ((c + STAGES - 1) % STAGES)*STAGE_BYTES,
                       A, B, K, m0, n0, (c + STAGES - 1)*BK, tid);
        CPA_COMMIT();

        const uint32_t st = sb + (c % STAGES)*STAGE_BYTES;
        #pragma unroll
        for (int ks = 0; ks < 2; ks++){
            uint32_t ah[2][4];
            #pragma unroll
            for (int mf = 0; mf < 2; mf++){
                uint32_t sw = swz(wm + mf*16 + frag_row, ks*2 + frag_u);
                ldm4(st + 0*MAT_BYTES + sw, ah[mf]);
            }
            #pragma unroll
            for (int np = 0; np < 4; np++){
                uint32_t sw = swz(wn + np*16 + frag_row, ks*2 + frag_u);
                uint32_t b4[4];
                ldm4(st + 1*MAT_BYTES + sw, b4);
                #pragma unroll
                for (int mf = 0; mf < 2; mf++){
                    mma16816(acc[mf][np*2],     ah[mf], b4[0], b4[2]);
                    mma16816(acc[mf][np*2 + 1], ah[mf], b4[1], b4[3]);
                }
            }
        }
        __syncthreads();
    }

    // epilogue
    const int gq = lane >> 2, c2 = (lane & 3) * 2;
    if (mode == 0){
        #pragma unroll
        for (int mf = 0; mf < 2; mf++){
            int r = m0 + wm + mf*16 + gq;
            #pragma unroll
            for (int nf = 0; nf < 8; nf++){
                int col = n0 + wn + nf*8 + c2;
                float b0 = __ldg(bias + col), b1 = __ldg(bias + col + 1);
                *reinterpret_cast<float2*>(&out[(size_t)r*DD + col]) =
                    make_float2(acc[mf][nf][0] + b0, acc[mf][nf][1] + b1);
                *reinterpret_cast<float2*>(&out[(size_t)(r+8)*DD + col]) =
                    make_float2(acc[mf][nf][2] + b0, acc[mf][nf][3] + b1);
            }
        }
    } else {
        #pragma unroll
        for (int mf = 0; mf < 2; mf++){
            int r = m0 + wm + mf*16 + gq;
            float br0 = __ldg(bias + r), br1 = __ldg(bias + r + 8);
            #pragma unroll
            for (int nf = 0; nf < 8; nf++){
                int col = n0 + wn + nf*8 + c2;     // sequence index
                int b = col >> 11, l = col & (LEN - 1);
                *reinterpret_cast<float2*>(&out[((size_t)(b*DOUT + r))*LEN + l]) =
                    make_float2(acc[mf][nf][0] + br0, acc[mf][nf][1] + br0);
                *reinterpret_cast<float2*>(&out[((size_t)(b*DOUT + r + 8))*LEN + l]) =
                    make_float2(acc[mf][nf][2] + br1, acc[mf][nf][3] + br1);
            }
        }
    }
}

// transpose + fp16 convert: src [R][C] fp32 -> dst [C][R] fp16
__global__ __launch_bounds__(256)
void tconv(const float* __restrict__ src, __half* __restrict__ dst,
           int R, int C){
    __shared__ float tile[32][33];
    const size_t zo = (size_t)blockIdx.z * R * C;
    const int c0 = blockIdx.x*32, r0 = blockIdx.y*32;
    #pragma unroll
    for (int i = threadIdx.y; i < 32; i += 8)
        tile[i][threadIdx.x] = src[zo + (size_t)(r0+i)*C + c0 + threadIdx.x];
    __syncthreads();
    #pragma unroll
    for (int i = threadIdx.y; i < 32; i += 8){
        float v = tile[threadIdx.x][i];
        dst[zo + (size_t)(c0+i)*R + r0 + threadIdx.x] = __float2half(v);
    }
}

// window-3 softmax attention; emits fp16 att
__global__ __launch_bounds__(256)
void attn_kernel(){
    for (int m = blockIdx.x; m < MM; m += gridDim.x){
        const int b = m >> 11, l = m & (LEN-1);
        const int head = threadIdx.x >> 5, lane = threadIdx.x & 31;
        const size_t base = (size_t)m*DD + head*64 + lane*2;
        const float2 q = *reinterpret_cast<const float2*>(&g_q[base]);
        float s[3]; float2 vv[3];
        #pragma unroll
        for (int w = 0; w < 3; w++){
            const int lw = l + w - 1;
            float2 kk = make_float2(0.f,0.f), v2 = make_float2(0.f,0.f);
            if (lw >= 0 && lw < LEN){
                const size_t off = (size_t)(b*LEN+lw)*DD + head*64 + lane*2;
                kk = *reinterpret_cast<const float2*>(&g_k[off]);
                v2 = *reinterpret_cast<const float2*>(&g_v[off]);
            }
            float p = q.x*kk.x + q.y*kk.y;
            #pragma unroll
            for (int o = 16; o; o >>= 1) p += __shfl_xor_sync(0xffffffffu, p, o);
            s[w] = p * 0.125f; vv[w] = v2;
        }
        const float mx = fmaxf(s[0], fmaxf(s[1], s[2]));
        const float e0 = __expf(s[0]-mx), e1 = __expf(s[1]-mx), e2 = __expf(s[2]-mx);
        const float inv = 1.f/(e0+e1+e2);
        const float ox = (e0*vv[0].x + e1*vv[1].x + e2*vv[2].x)*inv;
        const float oy = (e0*vv[0].y + e1*vv[1].y + e2*vv[2].y)*inv;
        __half2 h; h.x = __float2half(ox); h.y = __float2half(oy);
        *reinterpret_cast<__half2*>(&g_att[base]) = h;
    }
}

extern "C" void kernel_launch(void* const* d_in, const int* in_sizes, int n_in,
                              void* d_out, int out_size){
    const float* x  = (const float*)d_in[0];
    const float* Wq = (const float*)d_in[1];
    const float* bq = (const float*)d_in[2];
    const float* Wk = (const float*)d_in[3];
    const float* bk = (const float*)d_in[4];
    const float* Wv = (const float*)d_in[5];
    const float* bv = (const float*)d_in[6];
    const float* Wo = (const float*)d_in[7];
    const float* bo = (const float*)d_in[8];
    float* out = (float*)d_out;

    void *xt,*qw,*kw,*vw,*ow,*at,*pq,*pk,*pv;
    cudaGetSymbolAddress(&xt, g_xt);
    cudaGetSymbolAddress(&qw, g_wq);
    cudaGetSymbolAddress(&kw, g_wk);
    cudaGetSymbolAddress(&vw, g_wv);
    cudaGetSymbolAddress(&ow, g_wo);
    cudaGetSymbolAddress(&at, g_att);
    cudaGetSymbolAddress(&pq, g_q); cudaGetSymbolAddress(&pk, g_k);
    cudaGetSymbolAddress(&pv, g_v);

    cudaFuncSetAttribute(mma_gemm, cudaFuncAttributeMaxDynamicSharedMemorySize, SMEM_BYTES);

    dim3 tb(32, 8);
    tconv<<<dim3(LEN/32, NHID/32, BATCH), tb>>>(x, (__half*)xt, NHID, LEN);
    tconv<<<dim3(DD/32, NHID/32, 1), tb>>>(Wq, (__half*)qw, NHID, DD);
    tconv<<<dim3(DD/32, NHID/32, 1), tb>>>(Wk, (__half*)kw, NHID, DD);
    tconv<<<dim3(DD/32, NHID/32, 1), tb>>>(Wv, (__half*)vw, NHID, DD);
    tconv<<<dim3(DOUT/32, DD/32, 1), tb>>>(Wo, (__half*)ow, DD, DOUT);

    GemmArgs a1;
    a1.A = (const __half*)xt;
    a1.B[0] = (const __half*)qw;
    a1.B[1] = (const __half*)kw;
    a1.B[2] = (const __half*)vw;
    a1.bias[0] = bq; a1.bias[1] = bk; a1.bias[2] = bv;
    a1.out[0] = (float*)pq; a1.out[1] = (float*)pk; a1.out[2] = (float*)pv;
    mma_gemm<<<dim3(DD/BN, MM/BM, 3), NTHREADS, SMEM_BYTES>>>(a1, NHID, 0);

    attn_kernel<<<2048, 256>>>();

    GemmArgs a2;
    a2.A = (const __half*)ow;
    a2.B[0] = (const __half*)at;
    a2.B[1] = a2.B[0]; a2.B[2] = a2.B[0];
    a2.bias[0] = bo; a2.bias[1] = bo; a2.bias[2] = bo;
    a2.out[0] = out; a2.out[1] = out; a2.out[2] = out;
    mma_gemm<<<dim3(MM/BN, DOUT/BM, 1), NTHREADS, SMEM_BYTES>>>(a2, DD, 1);
}

// round 15
// speedup vs baseline: 2.2125x; 1.0534x over previous
#include <cuda_runtime.h>
#include <cuda_fp16.h>
#include <cstdint>

#define BATCH 8
#define NHID 256
#define LEN 2048
#define DD 512
#define DOUT 2048
#define MM (BATCH*LEN)

#define BM 128
#define BN 128
#define BK 32
#define NTHREADS 256
#define STAGES 5
#define MAT_BYTES 8192                    // 128 rows x 32 halves x 2B
#define STAGE_BYTES (2*MAT_BYTES)         // A, B
#define SMEM_BYTES (STAGES*STAGE_BYTES)   // 80KB -> 2 CTA/SM

// fp16 scratch
__device__ __align__(128) __half g_q[MM*DD];
__device__ __align__(128) __half g_k[MM*DD];
__device__ __align__(128) __half g_v[MM*DD];
__device__ __align__(128) __half g_xt[MM*NHID];
__device__ __align__(128) __half g_wq[DD*NHID];
__device__ __align__(128) __half g_wk[DD*NHID];
__device__ __align__(128) __half g_wv[DD*NHID];
__device__ __align__(128) __half g_wo[DOUT*DD];
__device__ __align__(128) __half g_att[MM*DD];

struct GemmArgs {
    const __half* A;
    const __half* B[3];
    const float* bias[3];
    void* out[3];          // mode 0: __half*, mode 1: float*
};
struct TconvArgs {
    const float* src[3];
    __half* dst[3];
};

__device__ __forceinline__ uint32_t s2u(const void* p){
    uint32_t a; asm("{ .reg .u64 t; cvta.to.shared.u64 t, %1; cvt.u32.u64 %0, t; }":"=r"(a):"l"(p)); return a; }
__device__ __forceinline__ void cpa16(uint32_t s, const void* g){
    asm volatile("cp.async.cg.shared.global [%0], [%1], 16;"::"r"(s),"l"(g):"memory"); }
#define CPA_COMMIT() asm volatile("cp.async.commit_group;":::"memory")
#define CPA_WAIT(n)  asm volatile("cp.async.wait_group %0;"::"n"(n):"memory")

__device__ __forceinline__ void ldm4(uint32_t a, uint32_t* r){
    asm volatile("ldmatrix.sync.aligned.m8n8.x4.shared.b16 {%0,%1,%2,%3}, [%4];"
        :"=r"(r[0]),"=r"(r[1]),"=r"(r[2]),"=r"(r[3]):"r"(a)); }
__device__ __forceinline__ void mma16816(float* d, const uint32_t* a,
                                         uint32_t b0, uint32_t b1){
    asm volatile("mma.sync.aligned.m16n8k16.row.col.f32.f16.f16.f32 "
        "{%0,%1,%2,%3}, {%4,%5,%6,%7}, {%8,%9}, {%0,%1,%2,%3};"
        :"+f"(d[0]),"+f"(d[1]),"+f"(d[2]),"+f"(d[3])
        :"r"(a[0]),"r"(a[1]),"r"(a[2]),"r"(a[3]),"r"(b0),"r"(b1)); }

// 16B-unit XOR swizzle: rows of 32 halves = 4 units; phys = r*4 + (u ^ ((r>>1)&3))
__device__ __forceinline__ uint32_t swz(int r, int u){
    return (uint32_t)((r*4 + (u ^ ((r>>1)&3))) * 16);
}

__device__ __forceinline__ void fill_stage(uint32_t sbase,
        const __half* __restrict__ A, const __half* __restrict__ B,
        int K, int m0, int n0, int k0, int tid){
    #pragma unroll
    for (int j = 0; j < 2; j++){
        int i = tid + j*NTHREADS;          // 0..511
        int r = i >> 2, u = i & 3;
        uint32_t sw = swz(r, u);
        size_t gA = (size_t)(m0 + r)*K + k0 + u*8;
        size_t gB = (size_t)(n0 + r)*K + k0 + u*8;
        cpa16(sbase + 0*MAT_BYTES + sw, A + gA);
        cpa16(sbase + 1*MAT_BYTES + sw, B + gB);
    }
}

// mode 0: half out[(m0+r)*DD + col] = acc + bias[col]          (GEMM1)
// mode 1: float out[(b*DOUT + r)*LEN + l] = acc + bias[r]      (GEMM2)
__global__ __launch_bounds__(NTHREADS, 2)
void mma_gemm(const __grid_constant__ GemmArgs args, int K, int mode){
    extern __shared__ __align__(1024) char smem[];
    const int z = blockIdx.z;
    const __half* __restrict__ A = args.A;
    const __half* __restrict__ B = args.B[z];
    const float* __restrict__ bias = args.bias[z];

    const uint32_t sb = s2u(smem);
    const int tid = threadIdx.x;
    const int wid = tid >> 5, lane = tid & 31;
    const int wm = (wid & 3) * 32;
    const int wn = (wid >> 2) * 64;
    const int m0 = blockIdx.y * BM;
    const int n0 = blockIdx.x * BN;
    const int NC = K / BK;

    const int g8 = lane >> 3;
    const int frag_row = ((g8 & 1) << 3) + (lane & 7);
    const int frag_u   = g8 >> 1;

    float acc[2][8][4];
    #pragma unroll
    for (int i = 0; i < 2; i++)
        #pragma unroll
        for (int j = 0; j < 8; j++)
            #pragma unroll
            for (int q = 0; q < 4; q++) acc[i][j][q] = 0.f;

    #pragma unroll
    for (int c = 0; c < STAGES - 1; c++){
        if (c < NC){
            fill_stage(sb + c*STAGE_BYTES, A, B, K, m0, n0, c*BK, tid);
        }
        CPA_COMMIT();
    }

    for (int c = 0; c < NC; c++){
        CPA_WAIT(STAGES - 2);
        __syncthreads();
        if (c + STAGES - 1 < NC)
            fill_stage(sb + ((c + STAGES - 1) % STAGES)*STAGE_BYTES,
                       A, B, K, m0, n0, (c + STAGES - 1)*BK, tid);
        CPA_COMMIT();

        const uint32_t st = sb + (c % STAGES)*STAGE_BYTES;
        #pragma unroll
        for (int ks = 0; ks < 2; ks++){
            uint32_t ah[2][4];
            #pragma unroll
            for (int mf = 0; mf < 2; mf++){
                uint32_t sw = swz(wm + mf*16 + frag_row, ks*2 + frag_u);
                ldm4(st + 0*MAT_BYTES + sw, ah[mf]);
            }
            #pragma unroll
            for (int np = 0; np < 4; np++){
                uint32_t sw = swz(wn + np*16 + frag_row, ks*2 + frag_u);
                uint32_t b4[4];
                ldm4(st + 1*MAT_BYTES + sw, b4);
                #pragma unroll
                for (int mf = 0; mf < 2; mf++){
                    mma16816(acc[mf][np*2],     ah[mf], b4[0], b4[2]);
                    mma16816(acc[mf][np*2 + 1], ah[mf], b4[1], b4[3]);
                }
            }
        }
        __syncthreads();
    }

    const int gq = lane >> 2, c2 = (lane & 3) * 2;
    if (mode == 0){
        __half* out = (__half*)args.out[z];
        #pragma unroll
        for (int mf = 0; mf < 2; mf++){
            int r = m0 + wm + mf*16 + gq;
            #pragma unroll
            for (int nf = 0; nf < 8; nf++){
                int col = n0 + wn + nf*8 + c2;
                float b0 = __ldg(bias + col), b1 = __ldg(bias + col + 1);
                __half2 h0 = __floats2half2_rn(acc[mf][nf][0] + b0, acc[mf][nf][1] + b1);
                __half2 h1 = __floats2half2_rn(acc[mf][nf][2] + b0, acc[mf][nf][3] + b1);
                *reinterpret_cast<__half2*>(&out[(size_t)r*DD + col]) = h0;
                *reinterpret_cast<__half2*>(&out[(size_t)(r+8)*DD + col]) = h1;
            }
        }
    } else {
        float* out = (float*)args.out[z];
        #pragma unroll
        for (int mf = 0; mf < 2; mf++){
            int r = m0 + wm + mf*16 + gq;
            float br0 = __ldg(bias + r), br1 = __ldg(bias + r + 8);
            #pragma unroll
            for (int nf = 0; nf < 8; nf++){
                int col = n0 + wn + nf*8 + c2;     // sequence index
                int b = col >> 11, l = col & (LEN - 1);
                *reinterpret_cast<float2*>(&out[((size_t)(b*DOUT + r))*LEN + l]) =
                    make_float2(acc[mf][nf][0] + br0, acc[mf][nf][1] + br0);
                *reinterpret_cast<float2*>(&out[((size_t)(b*DOUT + r + 8))*LEN + l]) =
                    make_float2(acc[mf][nf][2] + br1, acc[mf][nf][3] + br1);
            }
        }
    }
}

// transpose + fp16 convert: src[z] [R][C] fp32 -> dst[z] [C][R] fp16 (z per arg table)
__global__ __launch_bounds__(256)
void tconv3(const __grid_constant__ TconvArgs args, int R, int C){
    __shared__ float tile[32][33];
    const float* __restrict__ src = args.src[blockIdx.z];
    __half* __restrict__ dst = args.dst[blockIdx.z];
    const int c0 = blockIdx.x*32, r0 = blockIdx.y*32;
    #pragma unroll
    for (int i = threadIdx.y; i < 32; i += 8)
        tile[i][threadIdx.x] = src[(size_t)(r0+i)*C + c0 + threadIdx.x];
    __syncthreads();
    #pragma unroll
    for (int i = threadIdx.y; i < 32; i += 8){
        float v = tile[threadIdx.x][i];
        dst[(size_t)(c0+i)*R + r0 + threadIdx.x] = __float2half(v);
    }
}

// batched variant for x: z = batch slab
__global__ __launch_bounds__(256)
void tconvb(const float* __restrict__ src, __half* __restrict__ dst,
            int R, int C){
    __shared__ float tile[32][33];
    const size_t zo = (size_t)blockIdx.z * R * C;
    const int c0 = blockIdx.x*32, r0 = blockIdx.y*32;
    #pragma unroll
    for (int i = threadIdx.y; i < 32; i += 8)
        tile[i][threadIdx.x] = src[zo + (size_t)(r0+i)*C + c0 + threadIdx.x];
    __syncthreads();
    #pragma unroll
    for (int i = threadIdx.y; i < 32; i += 8){
        float v = tile[threadIdx.x][i];
        dst[zo + (size_t)(c0+i)*R + r0 + threadIdx.x] = __float2half(v);
    }
}

// window-3 softmax attention on fp16 q/k/v; emits fp16 att
__global__ __launch_bounds__(256)
void attn_kernel(){
    for (int m = blockIdx.x; m < MM; m += gridDim.x){
        const int b = m >> 11, l = m & (LEN-1);
        const int head = threadIdx.x >> 5, lane = threadIdx.x & 31;
        const size_t base = (size_t)m*DD + head*64 + lane*2;
        const float2 q = __half22float2(*reinterpret_cast<const __half2*>(&g_q[base]));
        float s[3]; float2 vv[3];
        #pragma unroll
        for (int w = 0; w < 3; w++){
            const int lw = l + w - 1;
            float2 kk = make_float2(0.f,0.f), v2 = make_float2(0.f,0.f);
            if (lw >= 0 && lw < LEN){
                const size_t off = (size_t)(b*LEN+lw)*DD + head*64 + lane*2;
                kk = __half22float2(*reinterpret_cast<const __half2*>(&g_k[off]));
                v2 = __half22float2(*reinterpret_cast<const __half2*>(&g_v[off]));
            }
            float p = q.x*kk.x + q.y*kk.y;
            #pragma unroll
            for (int o = 16; o; o >>= 1) p += __shfl_xor_sync(0xffffffffu, p, o);
            s[w] = p * 0.125f; vv[w] = v2;
        }
        const float mx = fmaxf(s[0], fmaxf(s[1], s[2]));
        const float e0 = __expf(s[0]-mx), e1 = __expf(s[1]-mx), e2 = __expf(s[2]-mx);
        const float inv = 1.f/(e0+e1+e2);
        const float ox = (e0*vv[0].x + e1*vv[1].x + e2*vv[2].x)*inv;
        const float oy = (e0*vv[0].y + e1*vv[1].y + e2*vv[2].y)*inv;
        *reinterpret_cast<__half2*>(&g_att[base]) = __floats2half2_rn(ox, oy);
    }
}

extern "C" void kernel_launch(void* const* d_in, const int* in_sizes, int n_in,
                              void* d_out, int out_size){
    const float* x  = (const float*)d_in[0];
    const float* Wq = (const float*)d_in[1];
    const float* bq = (const float*)d_in[2];
    const float* Wk = (const float*)d_in[3];
    const float* bk = (const float*)d_in[4];
    const float* Wv = (const float*)d_in[5];
    const float* bv = (const float*)d_in[6];
    const float* Wo = (const float*)d_in[7];
    const float* bo = (const float*)d_in[8];
    float* out = (float*)d_out;

    void *xt,*qw,*kw,*vw,*ow,*at,*pq,*pk,*pv;
    cudaGetSymbolAddress(&xt, g_xt);
    cudaGetSymbolAddress(&qw, g_wq);
    cudaGetSymbolAddress(&kw, g_wk);
    cudaGetSymbolAddress(&vw, g_wv);
    cudaGetSymbolAddress(&ow, g_wo);
    cudaGetSymbolAddress(&at, g_att);
    cudaGetSymbolAddress(&pq, g_q); cudaGetSymbolAddress(&pk, g_k);
    cudaGetSymbolAddress(&pv, g_v);

    cudaFuncSetAttribute(mma_gemm, cudaFuncAttributeMaxDynamicSharedMemorySize, SMEM_BYTES);

    dim3 tb(32, 8);
    tconvb<<<dim3(LEN/32, NHID/32, BATCH), tb>>>(x, (__half*)xt, NHID, LEN);
    TconvArgs tw;
    tw.src[0] = Wq; tw.src[1] = Wk; tw.src[2] = Wv;
    tw.dst[0] = (__half*)qw; tw.dst[1] = (__half*)kw; tw.dst[2] = (__half*)vw;
    tconv3<<<dim3(DD/32, NHID/32, 3), tb>>>(tw, NHID, DD);
    TconvArgs to;
    to.src[0] = Wo; to.src[1] = Wo; to.src[2] = Wo;
    to.dst[0] = (__half*)ow; to.dst[1] = (__half*)ow; to.dst[2] = (__half*)ow;
    tconv3<<<dim3(DOUT/32, DD/32, 1), tb>>>(to, DD, DOUT);

    GemmArgs a1;
    a1.A = (const __half*)xt;
    a1.B[0] = (const __half*)qw;
    a1.B[1] = (const __half*)kw;
    a1.B[2] = (const __half*)vw;
    a1.bias[0] = bq; a1.bias[1] = bk; a1.bias[2] = bv;
    a1.out[0] = pq; a1.out[1] = pk; a1.out[2] = pv;
    mma_gemm<<<dim3(DD/BN, MM/BM, 3), NTHREADS, SMEM_BYTES>>>(a1, NHID, 0);

    attn_kernel<<<2048, 256>>>();

    GemmArgs a2;
    a2.A = (const __half*)ow;
    a2.B[0] = (const __half*)at;
    a2.B[1] = a2.B[0]; a2.B[2] = a2.B[0];
    a2.bias[0] = bo; a2.bias[1] = bo; a2.bias[2] = bo;
    a2.out[0] = out; a2.out[1] = out; a2.out[2] = out;
    mma_gemm<<<dim3(MM/BN, DOUT/BM, 1), NTHREADS, SMEM_BYTES>>>(a2, DD, 1);
}